// round 15
// baseline (speedup 1.0000x reference)
#include <cuda_runtime.h>
#include <cuda_bf16.h>
#include <cstdint>
#include <math.h>

#define NN 100000
#define EMAX 1700000
#define NEG_SLOPE 0.2f

typedef unsigned long long u64;
typedef unsigned int u32;

// ---------------- scratch (device globals) ----------------
__device__ __align__(16) float g_h1[NN * 64];
__device__ __align__(16) float g_as1[NN * 8];
__device__ __align__(16) float g_ad1[NN * 8];
__device__ __align__(16) float g_hmid[NN * 64];
__device__ __align__(16) float g_h2[NN * 128];
__device__ __align__(16) float g_as2[NN];
__device__ __align__(16) float g_ad2[NN];
// W1 fragment table: [32 kblocks][8 nblocks][32 lanes] x uint4 {b0h,b1h,b0l,b1l}
__device__ __align__(16) uint4 g_w1f[32 * 8 * 32];
// W2 fragment table: [4 kblocks][16 nblocks][32 lanes]
__device__ __align__(16) uint4 g_w2f[4 * 16 * 32];
// CSR by destination
__device__ int g_cnt[NN];
__device__ int g_off[NN + 1];
__device__ int g_bsum[128];
__device__ int g_csr[EMAX];

// ---------------- helpers ----------------
__device__ __forceinline__ float leaky(float v) {
    return v > 0.0f ? v : NEG_SLOPE * v;
}
__device__ __forceinline__ void load_edge(const int* __restrict__ ei, int E,
                                          int idx, int& s, int& d) {
    if (idx < E) { s = ei[idx]; d = ei[E + idx]; }
    else         { s = d = idx - E; }
}

// pack 2 floats -> bf16x2 hi pair + bf16x2 lo (residual) pair.
__device__ __forceinline__ void cvt_hilo(float2 v, u32& hi, u32& lo) {
    u32 h;
    asm("cvt.rn.bf16x2.f32 %0, %1, %2;" : "=r"(h) : "f"(v.y), "f"(v.x));
    float xf = __uint_as_float(h << 16);
    float yf = __uint_as_float(h & 0xFFFF0000u);
    float lx = v.x - xf;
    float ly = v.y - yf;
    u32 l;
    asm("cvt.rn.bf16x2.f32 %0, %1, %2;" : "=r"(l) : "f"(ly), "f"(lx));
    hi = h; lo = l;
}

__device__ __forceinline__ void mma_bf16(float* d, const u32* a, u32 b0, u32 b1) {
    asm volatile(
        "mma.sync.aligned.m16n8k16.row.col.f32.bf16.bf16.f32 "
        "{%0,%1,%2,%3}, {%4,%5,%6,%7}, {%8,%9}, {%0,%1,%2,%3};"
        : "+f"(d[0]), "+f"(d[1]), "+f"(d[2]), "+f"(d[3])
        : "r"(a[0]), "r"(a[1]), "r"(a[2]), "r"(a[3]), "r"(b0), "r"(b1));
}

// ---------------- CSR build ----------------
__global__ __launch_bounds__(256)
void hist_kernel(const int* __restrict__ ei, int E, int Etot) {
    int idx = blockIdx.x * blockDim.x + threadIdx.x;
    if (idx >= Etot) return;
    int s, d; load_edge(ei, E, idx, s, d);
    atomicAdd(&g_cnt[d], 1);
}

__global__ __launch_bounds__(256)
void scan1_kernel(int n) {
    __shared__ int wsum[8];
    int blk = blockIdx.x;
    int tid = threadIdx.x;
    int i = blk * 1024 + tid * 4;
    int a0 = (i + 0 < n) ? g_cnt[i + 0] : 0;
    int a1 = (i + 1 < n) ? g_cnt[i + 1] : 0;
    int a2 = (i + 2 < n) ? g_cnt[i + 2] : 0;
    int a3 = (i + 3 < n) ? g_cnt[i + 3] : 0;
    int tsum = a0 + a1 + a2 + a3;
    int lane = tid & 31, wid = tid >> 5;
    int sc = tsum;
#pragma unroll
    for (int off = 1; off < 32; off <<= 1) {
        int t = __shfl_up_sync(0xFFFFFFFFu, sc, off);
        if (lane >= off) sc += t;
    }
    if (lane == 31) wsum[wid] = sc;
    __syncthreads();
    if (wid == 0) {
        int ws = (lane < 8) ? wsum[lane] : 0;
#pragma unroll
        for (int off = 1; off < 8; off <<= 1) {
            int t = __shfl_up_sync(0xFFFFFFFFu, ws, off);
            if (lane >= off) ws += t;
        }
        if (lane < 8) wsum[lane] = ws;
    }
    __syncthreads();
    int excl = sc - tsum + (wid > 0 ? wsum[wid - 1] : 0);
    if (i + 0 < n) g_off[i + 0] = excl;
    if (i + 1 < n) g_off[i + 1] = excl + a0;
    if (i + 2 < n) g_off[i + 2] = excl + a0 + a1;
    if (i + 3 < n) g_off[i + 3] = excl + a0 + a1 + a2;
    if (tid == 255) g_bsum[blk] = excl + tsum;
}

__global__ void scan2_kernel(int nb, int n) {
    int lane = threadIdx.x & 31;
    int v[4]; int s = 0;
#pragma unroll
    for (int i = 0; i < 4; i++) {
        int idx = lane * 4 + i;
        v[i] = (idx < nb) ? g_bsum[idx] : 0;
        s += v[i];
    }
    int sc = s;
#pragma unroll
    for (int off = 1; off < 32; off <<= 1) {
        int t = __shfl_up_sync(0xFFFFFFFFu, sc, off);
        if (lane >= off) sc += t;
    }
    int run = sc - s;
#pragma unroll
    for (int i = 0; i < 4; i++) {
        int idx = lane * 4 + i;
        int t = v[i];
        if (idx < nb) g_bsum[idx] = run;
        run += t;
    }
    if (lane == 31) g_off[n] = run;
}

__global__ __launch_bounds__(256)
void scan3_kernel(int n) {
    int i = blockIdx.x * blockDim.x + threadIdx.x;
    if (i < n) g_off[i] += g_bsum[i >> 10];
}

__global__ __launch_bounds__(256)
void scatter_kernel(const int* __restrict__ ei, int E, int Etot) {
    int idx = blockIdx.x * blockDim.x + threadIdx.x;
    if (idx >= Etot) return;
    int s, d; load_edge(ei, E, idx, s, d);
    int pos = g_off[d] + atomicAdd(&g_cnt[d], 1);
    g_csr[pos] = s;
}

// ---------------- weight fragment packers ----------------
__global__ __launch_bounds__(256)
void convw1_kernel(const float* __restrict__ W1) {
    int idx = blockIdx.x * blockDim.x + threadIdx.x;   // 32*8*32
    if (idx >= 32 * 8 * 32) return;
    int l  = idx & 31;
    int nb = (idx >> 5) & 7;
    int kb = idx >> 8;
    int n = nb * 8 + (l >> 2);
    int k = kb * 16 + 2 * (l & 3);
    float w00 = W1[(size_t)k * 64 + n];
    float w01 = W1[(size_t)(k + 1) * 64 + n];
    float w10 = W1[(size_t)(k + 8) * 64 + n];
    float w11 = W1[(size_t)(k + 9) * 64 + n];
    u32 b0h, b0l, b1h, b1l;
    cvt_hilo(make_float2(w00, w01), b0h, b0l);
    cvt_hilo(make_float2(w10, w11), b1h, b1l);
    g_w1f[idx] = make_uint4(b0h, b1h, b0l, b1l);
}

__global__ __launch_bounds__(256)
void convw2_kernel(const float* __restrict__ W2) {
    int idx = blockIdx.x * blockDim.x + threadIdx.x;   // 4*16*32
    if (idx >= 4 * 16 * 32) return;
    int l  = idx & 31;
    int nb = (idx >> 5) & 15;
    int kb = idx >> 9;
    int n = nb * 8 + (l >> 2);
    int k = kb * 16 + 2 * (l & 3);
    float w00 = W2[(size_t)k * 128 + n];
    float w01 = W2[(size_t)(k + 1) * 128 + n];
    float w10 = W2[(size_t)(k + 8) * 128 + n];
    float w11 = W2[(size_t)(k + 9) * 128 + n];
    u32 b0h, b0l, b1h, b1l;
    cvt_hilo(make_float2(w00, w01), b0h, b0l);
    cvt_hilo(make_float2(w10, w11), b1h, b1l);
    g_w2f[idx] = make_uint4(b0h, b1h, b0l, b1l);
}

// ---------------- unified register-direct bf16x3 mma GEMM ----------------
// CTA 128 rows x 64 cols; 8 warps, each a UNIQUE 16x64 tile (A read once).
// KT = K/16; TOTNB = total n-blocks per k-row in Btab; FUSE = alpha1 fusion.
// Output: columns [blockIdx.y*64, +64) of outp with row stride out_stride.
#define CPAD 68
#define OFF_ATTS (128 * CPAD * 4)
#define OFF_ATTD (OFF_ATTS + 256)
#define SM1_TOT  (OFF_ATTD + 256)

template<int KT, int TOTNB, bool FUSE>
__global__ __launch_bounds__(256)
void gemm_mma_kernel(const float* __restrict__ A, const uint4* __restrict__ Btab,
                     float* __restrict__ outp, int M, int out_stride,
                     const float* __restrict__ att_s, const float* __restrict__ att_d) {
    extern __shared__ char sm[];
    float* Cs = (float*)sm;
    float* atts = (float*)(sm + OFF_ATTS);
    float* attd = (float*)(sm + OFF_ATTD);
    const int tid = threadIdx.x;
    const int wid = tid >> 5;
    const int lane = tid & 31;
    const int bm = blockIdx.x * 128;
    const int nb_base = blockIdx.y * 8;
    const int col_off = blockIdx.y * 64;
    const int wm = wid * 16;
    const int g = lane >> 2;
    const int t2 = 2 * (lane & 3);
    const int K = KT * 16;

    if (FUSE && tid < 64) { atts[tid] = att_s[tid]; attd[tid] = att_d[tid]; }

    float d[8][4];
#pragma unroll
    for (int u = 0; u < 8; u++)
#pragma unroll
        for (int r = 0; r < 4; r++) d[u][r] = 0.f;

    int r0 = bm + wm + g;     if (r0 > M - 1) r0 = M - 1;
    int r1 = bm + wm + 8 + g; if (r1 > M - 1) r1 = M - 1;
    const float* pr0 = A + (size_t)r0 * K + t2;
    const float* pr1 = A + (size_t)r1 * K + t2;
    const uint4* pB = Btab + (size_t)nb_base * 32 + lane;

    for (int kt = 0; kt < KT; kt++) {
        const int k0 = kt * 16;
        float2 x0 = *(const float2*)(pr0 + k0);
        float2 x1 = *(const float2*)(pr1 + k0);
        float2 x2 = *(const float2*)(pr0 + k0 + 8);
        float2 x3 = *(const float2*)(pr1 + k0 + 8);
        u32 ah[4], al[4];
        cvt_hilo(x0, ah[0], al[0]);
        cvt_hilo(x1, ah[1], al[1]);
        cvt_hilo(x2, ah[2], al[2]);
        cvt_hilo(x3, ah[3], al[3]);
        const uint4* pk = pB + (size_t)kt * TOTNB * 32;
#pragma unroll
        for (int u = 0; u < 8; u++) {
            uint4 bf = pk[u * 32];
            mma_bf16(d[u], ah, bf.x, bf.y);
            mma_bf16(d[u], ah, bf.z, bf.w);
            mma_bf16(d[u], al, bf.x, bf.y);
        }
    }

    // accumulators -> smem C tile
#pragma unroll
    for (int u = 0; u < 8; u++) {
        int c = u * 8 + t2;
        *(float2*)&Cs[(wm + g) * CPAD + c]     = make_float2(d[u][0], d[u][1]);
        *(float2*)&Cs[(wm + 8 + g) * CPAD + c] = make_float2(d[u][2], d[u][3]);
    }
    __syncthreads();

    // final write: 2 threads per row, 32 cols each
    {
        int r = tid >> 1;
        int m = bm + r;
        int base = (tid & 1) * 32;
        if (m < M) {
            if (FUSE) {
                float as_acc[4] = {0.f, 0.f, 0.f, 0.f};
                float ad_acc[4] = {0.f, 0.f, 0.f, 0.f};
#pragma unroll
                for (int i = 0; i < 8; i++) {
                    int c = base + i * 4;
                    float4 v = *(const float4*)&Cs[r * CPAD + c];
                    *(float4*)&outp[(size_t)m * 64 + c] = v;
                    float4 sa = *(const float4*)&atts[c];
                    float4 da = *(const float4*)&attd[c];
                    int lh = i >> 1;
                    as_acc[lh] += v.x * sa.x + v.y * sa.y + v.z * sa.z + v.w * sa.w;
                    ad_acc[lh] += v.x * da.x + v.y * da.y + v.z * da.z + v.w * da.w;
                }
                int hb = (tid & 1) * 4;
                *(float4*)&g_as1[m * 8 + hb] = make_float4(as_acc[0], as_acc[1], as_acc[2], as_acc[3]);
                *(float4*)&g_ad1[m * 8 + hb] = make_float4(ad_acc[0], ad_acc[1], ad_acc[2], ad_acc[3]);
            } else {
#pragma unroll
                for (int i = 0; i < 8; i++) {
                    int c = base + i * 4;
                    *(float4*)&outp[(size_t)m * out_stride + col_off + c] =
                        *(const float4*)&Cs[r * CPAD + c];
                }
            }
        }
    }
}

// ---------------- layer2 alpha ----------------
__global__ __launch_bounds__(256)
void alpha2_kernel(const float* __restrict__ att_src, const float* __restrict__ att_dst,
                   int nnodes) {
    int gid = blockIdx.x * blockDim.x + threadIdx.x;
    int n = gid >> 5;
    int lane = gid & 31;
    if (n >= nnodes) return;
    float4 v = *(const float4*)&g_h2[(size_t)n * 128 + lane * 4];
    float4 a = ((const float4*)att_src)[lane];
    float4 b = ((const float4*)att_dst)[lane];
    float ss = v.x * a.x + v.y * a.y + v.z * a.z + v.w * a.w;
    float dd = v.x * b.x + v.y * b.y + v.z * b.z + v.w * b.w;
#pragma unroll
    for (int off = 16; off > 0; off >>= 1) {
        ss += __shfl_xor_sync(0xFFFFFFFFu, ss, off);
        dd += __shfl_xor_sync(0xFFFFFFFFu, dd, off);
    }
    if (lane == 0) { g_as2[n] = ss; g_ad2[n] = dd; }
}

// ---------------- aggregations ----------------
__global__ __launch_bounds__(256)
void agg1_kernel(const float* __restrict__ b1, int nnodes) {
    int gw = (blockIdx.x * 256 + threadIdx.x) >> 5;
    int lane = threadIdx.x & 31;
    if (gw >= nnodes) return;
    int h = lane >> 2;
    float ad = g_ad1[gw * 8 + h];
    int beg = g_off[gw], end = g_off[gw + 1];
    float ax = 0.f, ay = 0.f, denom = 0.f;
    int j = beg;
    for (; j + 4 <= end; j += 4) {
        int s0 = g_csr[j], s1 = g_csr[j + 1], s2 = g_csr[j + 2], s3 = g_csr[j + 3];
        float e0 = g_as1[s0 * 8 + h], e1 = g_as1[s1 * 8 + h];
        float e2 = g_as1[s2 * 8 + h], e3 = g_as1[s3 * 8 + h];
        float2 v0 = *(const float2*)&g_h1[s0 * 64 + lane * 2];
        float2 v1 = *(const float2*)&g_h1[s1 * 64 + lane * 2];
        float2 v2 = *(const float2*)&g_h1[s2 * 64 + lane * 2];
        float2 v3 = *(const float2*)&g_h1[s3 * 64 + lane * 2];
        float w0 = __expf(leaky(e0 + ad));
        float w1 = __expf(leaky(e1 + ad));
        float w2 = __expf(leaky(e2 + ad));
        float w3 = __expf(leaky(e3 + ad));
        ax += w0 * v0.x + w1 * v1.x + w2 * v2.x + w3 * v3.x;
        ay += w0 * v0.y + w1 * v1.y + w2 * v2.y + w3 * v3.y;
        denom += (w0 + w1) + (w2 + w3);
    }
    for (; j < end; j++) {
        int s = g_csr[j];
        float w = __expf(leaky(g_as1[s * 8 + h] + ad));
        float2 v = *(const float2*)&g_h1[s * 64 + lane * 2];
        ax += w * v.x; ay += w * v.y; denom += w;
    }
    float inv = 1.0f / denom;
    int c = lane * 2;
    float o0 = ax * inv + b1[c];
    float o1 = ay * inv + b1[c + 1];
    o0 = o0 > 0.f ? o0 : expm1f(o0);
    o1 = o1 > 0.f ? o1 : expm1f(o1);
    *(float2*)&g_hmid[gw * 64 + c] = make_float2(o0, o1);
}

__global__ __launch_bounds__(256)
void agg2_kernel(const float* __restrict__ b2, float* __restrict__ out, int nnodes) {
    int gw = (blockIdx.x * 256 + threadIdx.x) >> 5;
    int lane = threadIdx.x & 31;
    if (gw >= nnodes) return;
    float ad = g_ad2[gw];
    int beg = g_off[gw], end = g_off[gw + 1];
    float4 acc = make_float4(0.f, 0.f, 0.f, 0.f);
    float denom = 0.f;
    int j = beg;
    for (; j + 4 <= end; j += 4) {
        int s0 = g_csr[j], s1 = g_csr[j + 1], s2 = g_csr[j + 2], s3 = g_csr[j + 3];
        float e0 = g_as2[s0], e1 = g_as2[s1], e2 = g_as2[s2], e3 = g_as2[s3];
        float4 v0 = *(const float4*)&g_h2[(size_t)s0 * 128 + lane * 4];
        float4 v1 = *(const float4*)&g_h2[(size_t)s1 * 128 + lane * 4];
        float4 v2 = *(const float4*)&g_h2[(size_t)s2 * 128 + lane * 4];
        float4 v3 = *(const float4*)&g_h2[(size_t)s3 * 128 + lane * 4];
        float w0 = __expf(leaky(e0 + ad));
        float w1 = __expf(leaky(e1 + ad));
        float w2 = __expf(leaky(e2 + ad));
        float w3 = __expf(leaky(e3 + ad));
        acc.x += w0 * v0.x + w1 * v1.x + w2 * v2.x + w3 * v3.x;
        acc.y += w0 * v0.y + w1 * v1.y + w2 * v2.y + w3 * v3.y;
        acc.z += w0 * v0.z + w1 * v1.z + w2 * v2.z + w3 * v3.z;
        acc.w += w0 * v0.w + w1 * v1.w + w2 * v2.w + w3 * v3.w;
        denom += (w0 + w1) + (w2 + w3);
    }
    for (; j < end; j++) {
        int s = g_csr[j];
        float w = __expf(leaky(g_as2[s] + ad));
        float4 v = *(const float4*)&g_h2[(size_t)s * 128 + lane * 4];
        acc.x += w * v.x; acc.y += w * v.y; acc.z += w * v.z; acc.w += w * v.w;
        denom += w;
    }
    float inv = 1.0f / denom;
    float4 bb = ((const float4*)b2)[lane];
    float4 o = make_float4(acc.x * inv + bb.x, acc.y * inv + bb.y,
                           acc.z * inv + bb.z, acc.w * inv + bb.w);
    *(float4*)&out[(size_t)gw * 128 + lane * 4] = o;
}

// ---------------- launcher ----------------
static cudaStream_t g_side = nullptr;
static cudaEvent_t  g_ev_fork = nullptr, g_ev_csr = nullptr;

extern "C" void kernel_launch(void* const* d_in, const int* in_sizes, int n_in,
                              void* d_out, int out_size) {
    const float* x        = (const float*)d_in[0];
    const int*   ei       = (const int*)d_in[1];
    const float* W1       = (const float*)d_in[2];
    const float* att_src1 = (const float*)d_in[3];
    const float* att_dst1 = (const float*)d_in[4];
    const float* b1       = (const float*)d_in[5];
    const float* W2       = (const float*)d_in[6];
    const float* att_src2 = (const float*)d_in[7];
    const float* att_dst2 = (const float*)d_in[8];
    const float* b2       = (const float*)d_in[9];
    float* out = (float*)d_out;

    const int nnodes = in_sizes[0] / 512;
    const int E      = in_sizes[1] / 2;
    const int Etot   = E + nnodes;
    const int T = 256;
    const int NB = (nnodes + 1023) / 1024;

    if (!g_side) {
        cudaStreamCreateWithFlags(&g_side, cudaStreamNonBlocking);
        cudaEventCreateWithFlags(&g_ev_fork, cudaEventDisableTiming);
        cudaEventCreateWithFlags(&g_ev_csr,  cudaEventDisableTiming);
        cudaFuncSetAttribute((const void*)gemm_mma_kernel<32, 8, true>,
                             cudaFuncAttributeMaxDynamicSharedMemorySize, SM1_TOT);
        cudaFuncSetAttribute((const void*)gemm_mma_kernel<4, 16, false>,
                             cudaFuncAttributeMaxDynamicSharedMemorySize, SM1_TOT);
    }

    void* pcnt; cudaGetSymbolAddress(&pcnt, g_cnt);
    float *h1_ptr, *hmid_ptr, *h2_ptr;
    uint4 *w1f_ptr, *w2f_ptr;
    cudaGetSymbolAddress((void**)&h1_ptr, g_h1);
    cudaGetSymbolAddress((void**)&hmid_ptr, g_hmid);
    cudaGetSymbolAddress((void**)&h2_ptr, g_h2);
    cudaGetSymbolAddress((void**)&w1f_ptr, g_w1f);
    cudaGetSymbolAddress((void**)&w2f_ptr, g_w2f);

    // fork side stream for CSR build + W2 packing
    cudaEventRecord(g_ev_fork, 0);
    cudaStreamWaitEvent(g_side, g_ev_fork, 0);

    convw1_kernel<<<32, T>>>(W1);                                        // k1 (main)
    cudaMemsetAsync(pcnt, 0, (size_t)nnodes * 4, g_side);
    hist_kernel<<<(Etot + T - 1) / T, T, 0, g_side>>>(ei, E, Etot);      // k2
    scan1_kernel<<<NB, T, 0, g_side>>>(nnodes);                          // k3

    gemm_mma_kernel<32, 8, true><<<dim3((nnodes + 127) / 128, 1), T, SM1_TOT>>>(
        x, w1f_ptr, h1_ptr, nnodes, 64, att_src1, att_dst1);             // k4 (profiled)

    convw2_kernel<<<8, T, 0, g_side>>>(W2);                              // k5
    scan2_kernel<<<1, 32, 0, g_side>>>(NB, nnodes);                      // k6
    scan3_kernel<<<(nnodes + T - 1) / T, T, 0, g_side>>>(nnodes);        // k7
    cudaMemsetAsync(pcnt, 0, (size_t)nnodes * 4, g_side);
    scatter_kernel<<<(Etot + T - 1) / T, T, 0, g_side>>>(ei, E, Etot);   // k8
    cudaEventRecord(g_ev_csr, g_side);

    cudaStreamWaitEvent(0, g_ev_csr, 0);
    agg1_kernel<<<((size_t)nnodes * 32 + T - 1) / T, T>>>(b1, nnodes);   // k9

    gemm_mma_kernel<4, 16, false><<<dim3((nnodes + 127) / 128, 2), T, SM1_TOT>>>(
        hmid_ptr, w2f_ptr, h2_ptr, nnodes, 128, nullptr, nullptr);       // k10

    alpha2_kernel<<<((size_t)nnodes * 32 + T - 1) / T, T>>>(att_src2, att_dst2, nnodes); // k11
    agg2_kernel<<<((size_t)nnodes * 32 + T - 1) / T, T>>>(b2, out, nnodes);   // k12
}

// round 16
// speedup vs baseline: 1.0146x; 1.0146x over previous
#include <cuda_runtime.h>
#include <cuda_bf16.h>
#include <cstdint>
#include <math.h>

#define NN 100000
#define EMAX 1700000
#define NEG_SLOPE 0.2f

typedef unsigned long long u64;
typedef unsigned int u32;

// ---------------- scratch (device globals) ----------------
__device__ __align__(16) float g_h1[NN * 64];
__device__ __align__(16) float g_as1[NN * 8];
__device__ __align__(16) float g_ad1[NN * 8];
__device__ __align__(16) float g_hmid[NN * 64];
__device__ __align__(16) float g_h2[NN * 128];
__device__ __align__(16) float g_as2[NN];
__device__ __align__(16) float g_ad2[NN];
// W1 fragment table: [32 kblocks][8 nblocks][32 lanes] x uint4 {b0h,b1h,b0l,b1l}
__device__ __align__(16) uint4 g_w1f[32 * 8 * 32];
// W2 fragment table: [4 kblocks][16 nblocks][32 lanes]
__device__ __align__(16) uint4 g_w2f[4 * 16 * 32];
// CSR by destination
__device__ int g_cnt[NN];
__device__ int g_off[NN + 1];
__device__ int g_bsum[128];
__device__ int g_csr[EMAX];

// ---------------- helpers ----------------
__device__ __forceinline__ float leaky(float v) {
    return v > 0.0f ? v : NEG_SLOPE * v;
}
__device__ __forceinline__ void load_edge(const int* __restrict__ ei, int E,
                                          int idx, int& s, int& d) {
    if (idx < E) { s = ei[idx]; d = ei[E + idx]; }
    else         { s = d = idx - E; }
}

// pack 2 floats -> bf16x2 hi pair + bf16x2 lo (residual) pair.
__device__ __forceinline__ void cvt_hilo(float2 v, u32& hi, u32& lo) {
    u32 h;
    asm("cvt.rn.bf16x2.f32 %0, %1, %2;" : "=r"(h) : "f"(v.y), "f"(v.x));
    float xf = __uint_as_float(h << 16);
    float yf = __uint_as_float(h & 0xFFFF0000u);
    float lx = v.x - xf;
    float ly = v.y - yf;
    u32 l;
    asm("cvt.rn.bf16x2.f32 %0, %1, %2;" : "=r"(l) : "f"(ly), "f"(lx));
    hi = h; lo = l;
}

__device__ __forceinline__ void mma_bf16(float* d, const u32* a, u32 b0, u32 b1) {
    asm volatile(
        "mma.sync.aligned.m16n8k16.row.col.f32.bf16.bf16.f32 "
        "{%0,%1,%2,%3}, {%4,%5,%6,%7}, {%8,%9}, {%0,%1,%2,%3};"
        : "+f"(d[0]), "+f"(d[1]), "+f"(d[2]), "+f"(d[3])
        : "r"(a[0]), "r"(a[1]), "r"(a[2]), "r"(a[3]), "r"(b0), "r"(b1));
}

// ---------------- CSR build ----------------
__global__ __launch_bounds__(256)
void hist_kernel(const int* __restrict__ ei, int E, int Etot) {
    int idx = blockIdx.x * blockDim.x + threadIdx.x;
    if (idx >= Etot) return;
    int s, d; load_edge(ei, E, idx, s, d);
    atomicAdd(&g_cnt[d], 1);
}

__global__ __launch_bounds__(256)
void scan1_kernel(int n) {
    __shared__ int wsum[8];
    int blk = blockIdx.x;
    int tid = threadIdx.x;
    int i = blk * 1024 + tid * 4;
    int a0 = (i + 0 < n) ? g_cnt[i + 0] : 0;
    int a1 = (i + 1 < n) ? g_cnt[i + 1] : 0;
    int a2 = (i + 2 < n) ? g_cnt[i + 2] : 0;
    int a3 = (i + 3 < n) ? g_cnt[i + 3] : 0;
    int tsum = a0 + a1 + a2 + a3;
    int lane = tid & 31, wid = tid >> 5;
    int sc = tsum;
#pragma unroll
    for (int off = 1; off < 32; off <<= 1) {
        int t = __shfl_up_sync(0xFFFFFFFFu, sc, off);
        if (lane >= off) sc += t;
    }
    if (lane == 31) wsum[wid] = sc;
    __syncthreads();
    if (wid == 0) {
        int ws = (lane < 8) ? wsum[lane] : 0;
#pragma unroll
        for (int off = 1; off < 8; off <<= 1) {
            int t = __shfl_up_sync(0xFFFFFFFFu, ws, off);
            if (lane >= off) ws += t;
        }
        if (lane < 8) wsum[lane] = ws;
    }
    __syncthreads();
    int excl = sc - tsum + (wid > 0 ? wsum[wid - 1] : 0);
    if (i + 0 < n) g_off[i + 0] = excl;
    if (i + 1 < n) g_off[i + 1] = excl + a0;
    if (i + 2 < n) g_off[i + 2] = excl + a0 + a1;
    if (i + 3 < n) g_off[i + 3] = excl + a0 + a1 + a2;
    if (tid == 255) g_bsum[blk] = excl + tsum;
}

__global__ void scan2_kernel(int nb, int n) {
    int lane = threadIdx.x & 31;
    int v[4]; int s = 0;
#pragma unroll
    for (int i = 0; i < 4; i++) {
        int idx = lane * 4 + i;
        v[i] = (idx < nb) ? g_bsum[idx] : 0;
        s += v[i];
    }
    int sc = s;
#pragma unroll
    for (int off = 1; off < 32; off <<= 1) {
        int t = __shfl_up_sync(0xFFFFFFFFu, sc, off);
        if (lane >= off) sc += t;
    }
    int run = sc - s;
#pragma unroll
    for (int i = 0; i < 4; i++) {
        int idx = lane * 4 + i;
        int t = v[i];
        if (idx < nb) g_bsum[idx] = run;
        run += t;
    }
    if (lane == 31) g_off[n] = run;
}

__global__ __launch_bounds__(256)
void scan3_kernel(int n) {
    int i = blockIdx.x * blockDim.x + threadIdx.x;
    if (i < n) g_off[i] += g_bsum[i >> 10];
}

__global__ __launch_bounds__(256)
void scatter_kernel(const int* __restrict__ ei, int E, int Etot) {
    int idx = blockIdx.x * blockDim.x + threadIdx.x;
    if (idx >= Etot) return;
    int s, d; load_edge(ei, E, idx, s, d);
    int pos = g_off[d] + atomicAdd(&g_cnt[d], 1);
    g_csr[pos] = s;
}

// ---------------- weight fragment packers ----------------
__global__ __launch_bounds__(256)
void convw1_kernel(const float* __restrict__ W1) {
    int idx = blockIdx.x * blockDim.x + threadIdx.x;   // 32*8*32
    if (idx >= 32 * 8 * 32) return;
    int l  = idx & 31;
    int nb = (idx >> 5) & 7;
    int kb = idx >> 8;
    int n = nb * 8 + (l >> 2);
    int k = kb * 16 + 2 * (l & 3);
    float w00 = W1[(size_t)k * 64 + n];
    float w01 = W1[(size_t)(k + 1) * 64 + n];
    float w10 = W1[(size_t)(k + 8) * 64 + n];
    float w11 = W1[(size_t)(k + 9) * 64 + n];
    u32 b0h, b0l, b1h, b1l;
    cvt_hilo(make_float2(w00, w01), b0h, b0l);
    cvt_hilo(make_float2(w10, w11), b1h, b1l);
    g_w1f[idx] = make_uint4(b0h, b1h, b0l, b1l);
}

__global__ __launch_bounds__(256)
void convw2_kernel(const float* __restrict__ W2) {
    int idx = blockIdx.x * blockDim.x + threadIdx.x;   // 4*16*32
    if (idx >= 4 * 16 * 32) return;
    int l  = idx & 31;
    int nb = (idx >> 5) & 15;
    int kb = idx >> 9;
    int n = nb * 8 + (l >> 2);
    int k = kb * 16 + 2 * (l & 3);
    float w00 = W2[(size_t)k * 128 + n];
    float w01 = W2[(size_t)(k + 1) * 128 + n];
    float w10 = W2[(size_t)(k + 8) * 128 + n];
    float w11 = W2[(size_t)(k + 9) * 128 + n];
    u32 b0h, b0l, b1h, b1l;
    cvt_hilo(make_float2(w00, w01), b0h, b0l);
    cvt_hilo(make_float2(w10, w11), b1h, b1l);
    g_w2f[idx] = make_uint4(b0h, b1h, b0l, b1l);
}

#define CPAD 68
#define OFF_ATTS (128 * CPAD * 4)
#define OFF_ATTD (OFF_ATTS + 256)
#define SM1_TOT  (OFF_ATTD + 256)

// ---------------- GEMM1 (R14 config): 8 warps 4m x 2n, warp tile 32x32 -------
// Register-direct bf16x3 split; fused alpha1 epilogue.
__global__ __launch_bounds__(256)
void gemm1_mma_kernel(const float* __restrict__ A, int M,
                      const float* __restrict__ att_s, const float* __restrict__ att_d) {
    extern __shared__ char sm[];
    float* Cs = (float*)sm;
    float* atts = (float*)(sm + OFF_ATTS);
    float* attd = (float*)(sm + OFF_ATTD);
    const int tid = threadIdx.x;
    const int wid = tid >> 5;
    const int lane = tid & 31;
    const int bm = blockIdx.x * 128;
    const int wm = (wid >> 1) * 32;
    const int nb4 = (wid & 1) * 4;

    if (tid < 64) { atts[tid] = att_s[tid]; attd[tid] = att_d[tid]; }

    float d[2][4][4];
#pragma unroll
    for (int t = 0; t < 2; t++)
#pragma unroll
        for (int u = 0; u < 4; u++)
#pragma unroll
            for (int r = 0; r < 4; r++) d[t][u][r] = 0.f;

    const int g = lane >> 2;
    const int t2 = 2 * (lane & 3);
    const float* pr[4];
#pragma unroll
    for (int i = 0; i < 4; i++) {
        int r = bm + wm + i * 8 + g;
        if (r > M - 1) r = M - 1;
        pr[i] = A + (size_t)r * 512 + t2;
    }
    const uint4* pB = g_w1f + nb4 * 32 + lane;

    for (int kt = 0; kt < 32; kt++) {
        const int k0 = kt * 16;
        u32 ah[2][4], al[2][4];
#pragma unroll
        for (int t = 0; t < 2; t++) {
            float2 x0 = *(const float2*)(pr[2 * t]     + k0);
            float2 x1 = *(const float2*)(pr[2 * t + 1] + k0);
            float2 x2 = *(const float2*)(pr[2 * t]     + k0 + 8);
            float2 x3 = *(const float2*)(pr[2 * t + 1] + k0 + 8);
            cvt_hilo(x0, ah[t][0], al[t][0]);
            cvt_hilo(x1, ah[t][1], al[t][1]);
            cvt_hilo(x2, ah[t][2], al[t][2]);
            cvt_hilo(x3, ah[t][3], al[t][3]);
        }
        uint4 bf0 = pB[(kt * 8 + 0) * 32];
        uint4 bf1 = pB[(kt * 8 + 1) * 32];
        uint4 bf2 = pB[(kt * 8 + 2) * 32];
        uint4 bf3 = pB[(kt * 8 + 3) * 32];
#pragma unroll
        for (int t = 0; t < 2; t++) {
            mma_bf16(d[t][0], ah[t], bf0.x, bf0.y);
            mma_bf16(d[t][0], ah[t], bf0.z, bf0.w);
            mma_bf16(d[t][0], al[t], bf0.x, bf0.y);
            mma_bf16(d[t][1], ah[t], bf1.x, bf1.y);
            mma_bf16(d[t][1], ah[t], bf1.z, bf1.w);
            mma_bf16(d[t][1], al[t], bf1.x, bf1.y);
            mma_bf16(d[t][2], ah[t], bf2.x, bf2.y);
            mma_bf16(d[t][2], ah[t], bf2.z, bf2.w);
            mma_bf16(d[t][2], al[t], bf2.x, bf2.y);
            mma_bf16(d[t][3], ah[t], bf3.x, bf3.y);
            mma_bf16(d[t][3], ah[t], bf3.z, bf3.w);
            mma_bf16(d[t][3], al[t], bf3.x, bf3.y);
        }
    }

    const int wn = (wid & 1) * 32;
    __syncthreads();
#pragma unroll
    for (int t = 0; t < 2; t++) {
#pragma unroll
        for (int u = 0; u < 4; u++) {
            int r0 = wm + t * 16 + g;
            int c  = wn + u * 8 + t2;
            *(float2*)&Cs[r0 * CPAD + c]       = make_float2(d[t][u][0], d[t][u][1]);
            *(float2*)&Cs[(r0 + 8) * CPAD + c] = make_float2(d[t][u][2], d[t][u][3]);
        }
    }
    __syncthreads();

    {
        int r = tid >> 1;
        int m = bm + r;
        int base = (tid & 1) * 32;
        if (m < M) {
            float as_acc[4] = {0.f, 0.f, 0.f, 0.f};
            float ad_acc[4] = {0.f, 0.f, 0.f, 0.f};
#pragma unroll
            for (int i = 0; i < 8; i++) {
                int c = base + i * 4;
                float4 v = *(const float4*)&Cs[r * CPAD + c];
                *(float4*)&g_h1[(size_t)m * 64 + c] = v;
                float4 sa = *(const float4*)&atts[c];
                float4 da = *(const float4*)&attd[c];
                int lh = i >> 1;
                as_acc[lh] += v.x * sa.x + v.y * sa.y + v.z * sa.z + v.w * sa.w;
                ad_acc[lh] += v.x * da.x + v.y * da.y + v.z * da.z + v.w * da.w;
            }
            int hb = (tid & 1) * 4;
            *(float4*)&g_as1[m * 8 + hb] = make_float4(as_acc[0], as_acc[1], as_acc[2], as_acc[3]);
            *(float4*)&g_ad1[m * 8 + hb] = make_float4(ad_acc[0], ad_acc[1], ad_acc[2], ad_acc[3]);
        }
    }
}

// ---------------- GEMM2 (R15 template config KT=4, 16x64 warp bands) ---------
__global__ __launch_bounds__(256)
void gemm2_mma_kernel(const float* __restrict__ A, float* __restrict__ outp, int M) {
    extern __shared__ char sm[];
    float* Cs = (float*)sm;
    const int tid = threadIdx.x;
    const int wid = tid >> 5;
    const int lane = tid & 31;
    const int bm = blockIdx.x * 128;
    const int nb_base = blockIdx.y * 8;
    const int col_off = blockIdx.y * 64;
    const int wm = wid * 16;
    const int g = lane >> 2;
    const int t2 = 2 * (lane & 3);

    float d[8][4];
#pragma unroll
    for (int u = 0; u < 8; u++)
#pragma unroll
        for (int r = 0; r < 4; r++) d[u][r] = 0.f;

    int r0 = bm + wm + g;     if (r0 > M - 1) r0 = M - 1;
    int r1 = bm + wm + 8 + g; if (r1 > M - 1) r1 = M - 1;
    const float* pr0 = A + (size_t)r0 * 64 + t2;
    const float* pr1 = A + (size_t)r1 * 64 + t2;
    const uint4* pB = g_w2f + (size_t)nb_base * 32 + lane;

#pragma unroll
    for (int kt = 0; kt < 4; kt++) {
        const int k0 = kt * 16;
        float2 x0 = *(const float2*)(pr0 + k0);
        float2 x1 = *(const float2*)(pr1 + k0);
        float2 x2 = *(const float2*)(pr0 + k0 + 8);
        float2 x3 = *(const float2*)(pr1 + k0 + 8);
        u32 ah[4], al[4];
        cvt_hilo(x0, ah[0], al[0]);
        cvt_hilo(x1, ah[1], al[1]);
        cvt_hilo(x2, ah[2], al[2]);
        cvt_hilo(x3, ah[3], al[3]);
        const uint4* pk = pB + (size_t)kt * 16 * 32;
#pragma unroll
        for (int u = 0; u < 8; u++) {
            uint4 bf = pk[u * 32];
            mma_bf16(d[u], ah, bf.x, bf.y);
            mma_bf16(d[u], ah, bf.z, bf.w);
            mma_bf16(d[u], al, bf.x, bf.y);
        }
    }

#pragma unroll
    for (int u = 0; u < 8; u++) {
        int c = u * 8 + t2;
        *(float2*)&Cs[(wm + g) * CPAD + c]     = make_float2(d[u][0], d[u][1]);
        *(float2*)&Cs[(wm + 8 + g) * CPAD + c] = make_float2(d[u][2], d[u][3]);
    }
    __syncthreads();

    {
        int r = tid >> 1;
        int m = bm + r;
        int base = (tid & 1) * 32;
        if (m < M) {
#pragma unroll
            for (int i = 0; i < 8; i++) {
                int c = base + i * 4;
                *(float4*)&outp[(size_t)m * 128 + col_off + c] =
                    *(const float4*)&Cs[r * CPAD + c];
            }
        }
    }
}

// ---------------- layer2 alpha ----------------
__global__ __launch_bounds__(256)
void alpha2_kernel(const float* __restrict__ att_src, const float* __restrict__ att_dst,
                   int nnodes) {
    int gid = blockIdx.x * blockDim.x + threadIdx.x;
    int n = gid >> 5;
    int lane = gid & 31;
    if (n >= nnodes) return;
    float4 v = *(const float4*)&g_h2[(size_t)n * 128 + lane * 4];
    float4 a = ((const float4*)att_src)[lane];
    float4 b = ((const float4*)att_dst)[lane];
    float ss = v.x * a.x + v.y * a.y + v.z * a.z + v.w * a.w;
    float dd = v.x * b.x + v.y * b.y + v.z * b.z + v.w * b.w;
#pragma unroll
    for (int off = 16; off > 0; off >>= 1) {
        ss += __shfl_xor_sync(0xFFFFFFFFu, ss, off);
        dd += __shfl_xor_sync(0xFFFFFFFFu, dd, off);
    }
    if (lane == 0) { g_as2[n] = ss; g_ad2[n] = dd; }
}

// ---------------- aggregations ----------------
__global__ __launch_bounds__(256)
void agg1_kernel(const float* __restrict__ b1, int nnodes) {
    int gw = (blockIdx.x * 256 + threadIdx.x) >> 5;
    int lane = threadIdx.x & 31;
    if (gw >= nnodes) return;
    int h = lane >> 2;
    float ad = g_ad1[gw * 8 + h];
    int beg = g_off[gw], end = g_off[gw + 1];
    float ax = 0.f, ay = 0.f, denom = 0.f;
    int j = beg;
    for (; j + 4 <= end; j += 4) {
        int s0 = g_csr[j], s1 = g_csr[j + 1], s2 = g_csr[j + 2], s3 = g_csr[j + 3];
        float e0 = g_as1[s0 * 8 + h], e1 = g_as1[s1 * 8 + h];
        float e2 = g_as1[s2 * 8 + h], e3 = g_as1[s3 * 8 + h];
        float2 v0 = *(const float2*)&g_h1[s0 * 64 + lane * 2];
        float2 v1 = *(const float2*)&g_h1[s1 * 64 + lane * 2];
        float2 v2 = *(const float2*)&g_h1[s2 * 64 + lane * 2];
        float2 v3 = *(const float2*)&g_h1[s3 * 64 + lane * 2];
        float w0 = __expf(leaky(e0 + ad));
        float w1 = __expf(leaky(e1 + ad));
        float w2 = __expf(leaky(e2 + ad));
        float w3 = __expf(leaky(e3 + ad));
        ax += w0 * v0.x + w1 * v1.x + w2 * v2.x + w3 * v3.x;
        ay += w0 * v0.y + w1 * v1.y + w2 * v2.y + w3 * v3.y;
        denom += (w0 + w1) + (w2 + w3);
    }
    for (; j < end; j++) {
        int s = g_csr[j];
        float w = __expf(leaky(g_as1[s * 8 + h] + ad));
        float2 v = *(const float2*)&g_h1[s * 64 + lane * 2];
        ax += w * v.x; ay += w * v.y; denom += w;
    }
    float inv = 1.0f / denom;
    int c = lane * 2;
    float o0 = ax * inv + b1[c];
    float o1 = ay * inv + b1[c + 1];
    o0 = o0 > 0.f ? o0 : expm1f(o0);
    o1 = o1 > 0.f ? o1 : expm1f(o1);
    *(float2*)&g_hmid[gw * 64 + c] = make_float2(o0, o1);
}

__global__ __launch_bounds__(256)
void agg2_kernel(const float* __restrict__ b2, float* __restrict__ out, int nnodes) {
    int gw = (blockIdx.x * 256 + threadIdx.x) >> 5;
    int lane = threadIdx.x & 31;
    if (gw >= nnodes) return;
    float ad = g_ad2[gw];
    int beg = g_off[gw], end = g_off[gw + 1];
    float4 acc = make_float4(0.f, 0.f, 0.f, 0.f);
    float denom = 0.f;
    int j = beg;
    for (; j + 4 <= end; j += 4) {
        int s0 = g_csr[j], s1 = g_csr[j + 1], s2 = g_csr[j + 2], s3 = g_csr[j + 3];
        float e0 = g_as2[s0], e1 = g_as2[s1], e2 = g_as2[s2], e3 = g_as2[s3];
        float4 v0 = *(const float4*)&g_h2[(size_t)s0 * 128 + lane * 4];
        float4 v1 = *(const float4*)&g_h2[(size_t)s1 * 128 + lane * 4];
        float4 v2 = *(const float4*)&g_h2[(size_t)s2 * 128 + lane * 4];
        float4 v3 = *(const float4*)&g_h2[(size_t)s3 * 128 + lane * 4];
        float w0 = __expf(leaky(e0 + ad));
        float w1 = __expf(leaky(e1 + ad));
        float w2 = __expf(leaky(e2 + ad));
        float w3 = __expf(leaky(e3 + ad));
        acc.x += w0 * v0.x + w1 * v1.x + w2 * v2.x + w3 * v3.x;
        acc.y += w0 * v0.y + w1 * v1.y + w2 * v2.y + w3 * v3.y;
        acc.z += w0 * v0.z + w1 * v1.z + w2 * v2.z + w3 * v3.z;
        acc.w += w0 * v0.w + w1 * v1.w + w2 * v2.w + w3 * v3.w;
        denom += (w0 + w1) + (w2 + w3);
    }
    for (; j < end; j++) {
        int s = g_csr[j];
        float w = __expf(leaky(g_as2[s] + ad));
        float4 v = *(const float4*)&g_h2[(size_t)s * 128 + lane * 4];
        acc.x += w * v.x; acc.y += w * v.y; acc.z += w * v.z; acc.w += w * v.w;
        denom += w;
    }
    float inv = 1.0f / denom;
    float4 bb = ((const float4*)b2)[lane];
    float4 o = make_float4(acc.x * inv + bb.x, acc.y * inv + bb.y,
                           acc.z * inv + bb.z, acc.w * inv + bb.w);
    *(float4*)&out[(size_t)gw * 128 + lane * 4] = o;
}

// ---------------- launcher ----------------
static cudaStream_t g_side = nullptr;
static cudaEvent_t  g_ev_fork = nullptr, g_ev_csr = nullptr;

extern "C" void kernel_launch(void* const* d_in, const int* in_sizes, int n_in,
                              void* d_out, int out_size) {
    const float* x        = (const float*)d_in[0];
    const int*   ei       = (const int*)d_in[1];
    const float* W1       = (const float*)d_in[2];
    const float* att_src1 = (const float*)d_in[3];
    const float* att_dst1 = (const float*)d_in[4];
    const float* b1       = (const float*)d_in[5];
    const float* W2       = (const float*)d_in[6];
    const float* att_src2 = (const float*)d_in[7];
    const float* att_dst2 = (const float*)d_in[8];
    const float* b2       = (const float*)d_in[9];
    float* out = (float*)d_out;

    const int nnodes = in_sizes[0] / 512;
    const int E      = in_sizes[1] / 2;
    const int Etot   = E + nnodes;
    const int T = 256;
    const int NB = (nnodes + 1023) / 1024;

    if (!g_side) {
        cudaStreamCreateWithFlags(&g_side, cudaStreamNonBlocking);
        cudaEventCreateWithFlags(&g_ev_fork, cudaEventDisableTiming);
        cudaEventCreateWithFlags(&g_ev_csr,  cudaEventDisableTiming);
        cudaFuncSetAttribute(gemm1_mma_kernel,
                             cudaFuncAttributeMaxDynamicSharedMemorySize, SM1_TOT);
        cudaFuncSetAttribute(gemm2_mma_kernel,
                             cudaFuncAttributeMaxDynamicSharedMemorySize, SM1_TOT);
    }

    void* pcnt; cudaGetSymbolAddress(&pcnt, g_cnt);
    float *h1_ptr, *hmid_ptr, *h2_ptr;
    cudaGetSymbolAddress((void**)&h1_ptr, g_h1);
    cudaGetSymbolAddress((void**)&hmid_ptr, g_hmid);
    cudaGetSymbolAddress((void**)&h2_ptr, g_h2);

    // fork side stream for CSR build + W2 packing
    cudaEventRecord(g_ev_fork, 0);
    cudaStreamWaitEvent(g_side, g_ev_fork, 0);

    convw1_kernel<<<32, T>>>(W1);                                        // k1 (main)
    cudaMemsetAsync(pcnt, 0, (size_t)nnodes * 4, g_side);
    hist_kernel<<<(Etot + T - 1) / T, T, 0, g_side>>>(ei, E, Etot);      // k2
    scan1_kernel<<<NB, T, 0, g_side>>>(nnodes);                          // k3

    gemm1_mma_kernel<<<(nnodes + 127) / 128, T, SM1_TOT>>>(x, nnodes,    // k4 (profiled)
                                                           att_src1, att_dst1);

    convw2_kernel<<<8, T, 0, g_side>>>(W2);                              // k5
    scan2_kernel<<<1, 32, 0, g_side>>>(NB, nnodes);                      // k6
    scan3_kernel<<<(nnodes + T - 1) / T, T, 0, g_side>>>(nnodes);        // k7
    cudaMemsetAsync(pcnt, 0, (size_t)nnodes * 4, g_side);
    scatter_kernel<<<(Etot + T - 1) / T, T, 0, g_side>>>(ei, E, Etot);   // k8
    cudaEventRecord(g_ev_csr, g_side);

    cudaStreamWaitEvent(0, g_ev_csr, 0);
    agg1_kernel<<<((size_t)nnodes * 32 + T - 1) / T, T>>>(b1, nnodes);   // k9

    gemm2_mma_kernel<<<dim3((nnodes + 127) / 128, 2), T, SM1_TOT>>>(
        hmid_ptr, h2_ptr, nnodes);                                       // k10

    alpha2_kernel<<<((size_t)nnodes * 32 + T - 1) / T, T>>>(att_src2, att_dst2, nnodes); // k11
    agg2_kernel<<<((size_t)nnodes * 32 + T - 1) / T, T>>>(b2, out, nnodes);   // k12
}